// round 1
// baseline (speedup 1.0000x reference)
#include <cuda_runtime.h>
#include <math.h>
#include <float.h>

// Problem constants
#define B_    4
#define NSEQ  4096
#define DIM   1024
#define H_    16
#define DH    64
#define WS    128
#define NW    32          // NSEQ / WS
#define JW    256         // (backward+forward+1) * WS
#define QKVC  3072
#define M1    (B_ * NSEQ) // 16384

// Scratch (no cudaMalloc allowed) — allocated at module load
__device__ float g_qkv[(size_t)M1 * QKVC]; // 192 MB
__device__ float g_att[(size_t)M1 * DIM];  // 64 MB

// ---------------------------------------------------------------------------
// SGEMM: C[M,N] = A[M,K] @ B[K,N], all row-major. BM=BN=128, BK=8, TM=TN=8.
// ---------------------------------------------------------------------------
#define BM 128
#define BN 128
#define BK 8
#define TM 8
#define TN 8

__global__ __launch_bounds__(256) void sgemm_kernel(
    int M, int N, int K,
    const float* __restrict__ A,
    const float* __restrict__ B,
    float* __restrict__ C)
{
    const int cRow = blockIdx.y;
    const int cCol = blockIdx.x;

    __shared__ float As[BK * BM];
    __shared__ float Bs[BK * BN];

    const int tid = threadIdx.x;
    const int threadCol = tid % (BN / TN); // 0..15
    const int threadRow = tid / (BN / TN); // 0..15

    A += (size_t)cRow * BM * K;
    B += cCol * BN;
    C += (size_t)cRow * BM * N + cCol * BN;

    const int innerRowA = tid / (BK / 4); // 0..127
    const int innerColA = tid % (BK / 4); // 0..1
    const int innerRowB = tid / (BN / 4); // 0..7
    const int innerColB = tid % (BN / 4); // 0..31

    float acc[TM * TN];
    #pragma unroll
    for (int i = 0; i < TM * TN; ++i) acc[i] = 0.0f;
    float regM[TM], regN[TN];

    for (int bk = 0; bk < K; bk += BK) {
        float4 ta = *(const float4*)&A[(size_t)innerRowA * K + innerColA * 4];
        As[(innerColA * 4 + 0) * BM + innerRowA] = ta.x;
        As[(innerColA * 4 + 1) * BM + innerRowA] = ta.y;
        As[(innerColA * 4 + 2) * BM + innerRowA] = ta.z;
        As[(innerColA * 4 + 3) * BM + innerRowA] = ta.w;
        *(float4*)&Bs[innerRowB * BN + innerColB * 4] =
            *(const float4*)&B[(size_t)innerRowB * N + innerColB * 4];
        __syncthreads();

        A += BK;
        B += (size_t)BK * N;

        #pragma unroll
        for (int k = 0; k < BK; ++k) {
            #pragma unroll
            for (int i = 0; i < TM; ++i) regM[i] = As[k * BM + threadRow * TM + i];
            #pragma unroll
            for (int j = 0; j < TN; ++j) regN[j] = Bs[k * BN + threadCol * TN + j];
            #pragma unroll
            for (int i = 0; i < TM; ++i)
                #pragma unroll
                for (int j = 0; j < TN; ++j)
                    acc[i * TN + j] += regM[i] * regN[j];
        }
        __syncthreads();
    }

    #pragma unroll
    for (int i = 0; i < TM; ++i) {
        #pragma unroll
        for (int j = 0; j < TN; j += 4) {
            float4 t;
            t.x = acc[i * TN + j + 0];
            t.y = acc[i * TN + j + 1];
            t.z = acc[i * TN + j + 2];
            t.w = acc[i * TN + j + 3];
            *(float4*)&C[(size_t)(threadRow * TM + i) * N + threadCol * TN + j] = t;
        }
    }
}

// ---------------------------------------------------------------------------
// Local attention: one block per (b, h, w). 128 threads, thread i = query i.
// smem: sK[256][64] (reused for V) + sS[128][257] score buffer.
// Valid keys for query i: j in [i, i+128], and j >= 128 when w == 0.
// RoPE positions are window-relative: q -> 128+i, k -> j.
// ---------------------------------------------------------------------------
#define SROW 257
#define ATTN_SMEM_BYTES ((JW * DH + WS * SROW) * (int)sizeof(float))

__global__ __launch_bounds__(128) void attn_kernel()
{
    extern __shared__ float smem[];
    float* sK = smem;             // [256][64]
    float* sS = smem + JW * DH;   // [128][257]

    const int blk = blockIdx.x;
    const int w = blk & (NW - 1);
    const int h = (blk >> 5) & (H_ - 1);
    const int b = blk >> 9;
    const int tid = threadIdx.x;
    const size_t base = (size_t)b * NSEQ;

    const float RC = 0.28782313662425575f; // ln(10000)/32

    // --- load K tile (window w-1 .. w), pad with 0 (masked anyway) ---
    #pragma unroll 4
    for (int it = 0; it < 32; ++it) {
        int idx4 = it * 128 + tid;
        int j  = idx4 >> 4;
        int d4 = idx4 & 15;
        int p  = w * WS - WS + j;
        float4 v = make_float4(0.f, 0.f, 0.f, 0.f);
        if (p >= 0)
            v = *(const float4*)&g_qkv[(base + p) * QKVC + DIM + h * DH + d4 * 4];
        *(float4*)&sK[j * DH + d4 * 4] = v;
    }
    __syncthreads();

    // --- RoPE K in place (position = j) ---
    for (int it = 0; it < 64; ++it) {
        int idx = it * 128 + tid;
        int j = idx >> 5;
        int m = idx & 31;
        float f = (float)j * expf(-(float)m * RC);
        float c = cosf(f), s = sinf(f);
        float k0 = sK[j * DH + m];
        float k1 = sK[j * DH + m + 32];
        sK[j * DH + m]      = k0 * c - k1 * s;
        sK[j * DH + m + 32] = k1 * c + k0 * s;
    }
    __syncthreads();

    const int i = tid;

    // --- load + scale + RoPE q (position = 128 + i) ---
    float q[DH];
    {
        const float4* qr = (const float4*)&g_qkv[(base + w * WS + i) * QKVC + h * DH];
        #pragma unroll
        for (int d4 = 0; d4 < 16; ++d4) {
            float4 v = qr[d4];
            q[d4 * 4 + 0] = v.x * 0.125f;
            q[d4 * 4 + 1] = v.y * 0.125f;
            q[d4 * 4 + 2] = v.z * 0.125f;
            q[d4 * 4 + 3] = v.w * 0.125f;
        }
        float pos = (float)(WS + i);
        #pragma unroll
        for (int m = 0; m < 32; ++m) {
            float f = pos * expf(-(float)m * RC);
            float c = cosf(f), s = sinf(f);
            float q0 = q[m], q1 = q[m + 32];
            q[m]      = q0 * c - q1 * s;
            q[m + 32] = q1 * c + q0 * s;
        }
    }

    const int jlo = (w == 0) ? WS : i;
    const int jhi = i + WS; // inclusive

    // --- scores for valid keys only ---
    for (int j = jlo; j <= jhi; ++j) {
        const float4* kr = (const float4*)&sK[j * DH];
        float a0 = 0.f, a1 = 0.f, a2 = 0.f, a3 = 0.f;
        #pragma unroll
        for (int d4 = 0; d4 < 16; ++d4) {
            float4 kv = kr[d4];
            a0 += q[d4 * 4 + 0] * kv.x;
            a1 += q[d4 * 4 + 1] * kv.y;
            a2 += q[d4 * 4 + 2] * kv.z;
            a3 += q[d4 * 4 + 3] * kv.w;
        }
        sS[i * SROW + j] = (a0 + a1) + (a2 + a3);
    }
    __syncthreads(); // all score reads of sK done before overwriting with V

    // --- load V tile over sK (no RoPE on V) ---
    #pragma unroll 4
    for (int it = 0; it < 32; ++it) {
        int idx4 = it * 128 + tid;
        int j  = idx4 >> 4;
        int d4 = idx4 & 15;
        int p  = w * WS - WS + j;
        float4 v = make_float4(0.f, 0.f, 0.f, 0.f);
        if (p >= 0)
            v = *(const float4*)&g_qkv[(base + p) * QKVC + 2 * DIM + h * DH + d4 * 4];
        *(float4*)&sK[j * DH + d4 * 4] = v;
    }

    // --- softmax over own row (no sync needed: own data only) ---
    float mmax = -FLT_MAX;
    for (int j = jlo; j <= jhi; ++j) mmax = fmaxf(mmax, sS[i * SROW + j]);
    float sum = 0.f;
    for (int j = jlo; j <= jhi; ++j) {
        float e = expf(sS[i * SROW + j] - mmax);
        sS[i * SROW + j] = e;
        sum += e;
    }
    const float inv = 1.0f / sum;
    __syncthreads(); // V visible to all

    // --- P @ V ---
    float acc[DH];
    #pragma unroll
    for (int d = 0; d < DH; ++d) acc[d] = 0.f;
    for (int j = jlo; j <= jhi; ++j) {
        float p = sS[i * SROW + j] * inv;
        const float4* vr = (const float4*)&sK[j * DH];
        #pragma unroll
        for (int d4 = 0; d4 < 16; ++d4) {
            float4 vv = vr[d4];
            acc[d4 * 4 + 0] += p * vv.x;
            acc[d4 * 4 + 1] += p * vv.y;
            acc[d4 * 4 + 2] += p * vv.z;
            acc[d4 * 4 + 3] += p * vv.w;
        }
    }

    float* orow = &g_att[(base + w * WS + i) * DIM + h * DH];
    #pragma unroll
    for (int d4 = 0; d4 < 16; ++d4)
        *(float4*)&orow[d4 * 4] =
            make_float4(acc[d4 * 4], acc[d4 * 4 + 1], acc[d4 * 4 + 2], acc[d4 * 4 + 3]);
}

// ---------------------------------------------------------------------------
extern "C" void kernel_launch(void* const* d_in, const int* in_sizes, int n_in,
                              void* d_out, int out_size)
{
    const float* x    = (const float*)d_in[0]; // [16384, 1024]
    const float* Wqkv = (const float*)d_in[1]; // [1024, 3072]
    const float* Wout = (const float*)d_in[2]; // [1024, 1024]
    float* out = (float*)d_out;                // [16384, 1024]

    float* qkv = nullptr;
    float* att = nullptr;
    cudaGetSymbolAddress((void**)&qkv, g_qkv);
    cudaGetSymbolAddress((void**)&att, g_att);

    cudaFuncSetAttribute(attn_kernel,
                         cudaFuncAttributeMaxDynamicSharedMemorySize,
                         ATTN_SMEM_BYTES);

    // 1) QKV projection
    {
        dim3 grid(QKVC / BN, M1 / BM); // (24, 128)
        sgemm_kernel<<<grid, 256>>>(M1, QKVC, DIM, x, Wqkv, qkv);
    }
    // 2) Windowed attention with RoPE
    {
        attn_kernel<<<B_ * H_ * NW, 128, ATTN_SMEM_BYTES>>>();
    }
    // 3) Output projection
    {
        dim3 grid(DIM / BN, M1 / BM); // (8, 128)
        sgemm_kernel<<<grid, 256>>>(M1, DIM, DIM, att, Wout, out);
    }
}